// round 16
// baseline (speedup 1.0000x reference)
#include <cuda_runtime.h>
#include <cuda_bf16.h>
#include <cuda_fp16.h>
#include <math.h>
#include <stdint.h>

#define HEADS   8
#define NBUCK   64
#define BSZ     64
#define DH      128
#define DMODEL  1024
#define TLEN    4096
#define NB      2
#define BH      16          // NB*HEADS
#define NROWS   8192        // NB*TLEN
#define QKVC    3072
#define TEMP_   0.75f
#define EPS_    1e-6f
#define SCALE_  0.03125f    // 1024^-0.5

// ------------------------- device scratch (no allocs allowed) ----------------
__device__ float   g_sx[128 * 2048];                // bucket-sum @ W (fp32)
__device__ int     g_idx[BH * NBUCK];
__device__ float   g_val[BH * NBUCK];
__device__ __half  g_x0[(size_t)NROWS * DMODEL];    // x fp16
__device__ __half  g_S[128 * DMODEL];               // bucket sums of x, fp16
__device__ __half  g_wq0[(size_t)QKVC * DMODEL];    // w_qkv^T hi
__device__ __half  g_wq1[(size_t)QKVC * DMODEL];    // w_qkv^T lo
__device__ __half  g_wo0[(size_t)DMODEL * DMODEL];  // w_out^T hi
__device__ __half  g_wo1[(size_t)DMODEL * DMODEL];  // w_out^T lo
__device__ __half  g_qh[(size_t)NROWS * DMODEL];    // q fp16
__device__ __half  g_kh[(size_t)NROWS * DMODEL];    // k hi
__device__ __half  g_kl[(size_t)NROWS * DMODEL];    // k lo
__device__ __half  g_vh[(size_t)NROWS * DMODEL];    // v hi
__device__ __half  g_vl[(size_t)NROWS * DMODEL];    // v lo
__device__ __half  g_ao0[(size_t)NROWS * DMODEL];   // attn out fp16

// ------------------------- helpers -------------------------------------------
#define SWZ(o) ((uint32_t)(o) ^ ((((uint32_t)(o)) >> 3) & 0x70u))

__device__ __forceinline__ uint32_t s2u(const void* p) {
    uint32_t a;
    asm("{ .reg .u64 t; cvta.to.shared.u64 t, %1; cvt.u32.u64 %0, t; }" : "=r"(a) : "l"(p));
    return a;
}

__device__ __forceinline__ void cp16(uint32_t s, const void* g) {
    asm volatile("cp.async.cg.shared.global [%0], [%1], 16;\n" :: "r"(s), "l"(g));
}

__device__ __forceinline__ void ldm4(uint32_t addr, uint32_t* r) {
    asm volatile("ldmatrix.sync.aligned.m8n8.x4.shared.b16 {%0,%1,%2,%3}, [%4];"
                 : "=r"(r[0]), "=r"(r[1]), "=r"(r[2]), "=r"(r[3]) : "r"(addr));
}

__device__ __forceinline__ void ldm4t(uint32_t addr, uint32_t* r) {
    asm volatile("ldmatrix.sync.aligned.m8n8.x4.trans.shared.b16 {%0,%1,%2,%3}, [%4];"
                 : "=r"(r[0]), "=r"(r[1]), "=r"(r[2]), "=r"(r[3]) : "r"(addr));
}

__device__ __forceinline__ void mma16816(float* c, const uint32_t* a, const uint32_t* b) {
    asm volatile(
        "mma.sync.aligned.m16n8k16.row.col.f32.f16.f16.f32 "
        "{%0,%1,%2,%3}, {%4,%5,%6,%7}, {%8,%9}, {%0,%1,%2,%3};"
        : "+f"(c[0]), "+f"(c[1]), "+f"(c[2]), "+f"(c[3])
        : "r"(a[0]), "r"(a[1]), "r"(a[2]), "r"(a[3]), "r"(b[0]), "r"(b[1]));
}

__device__ __forceinline__ __half2 split_hi(float a, float b, __half2& lo) {
    __half h0 = __float2half_rn(a), h1 = __float2half_rn(b);
    lo = __halves2half2(__float2half_rn(a - __half2float(h0)),
                        __float2half_rn(b - __half2float(h1)));
    return __halves2half2(h0, h1);
}

// ------------------------- fp16 HMMA GEMM ------------------------------------
// C = A0 @ (B0 + B1)^T. Columns < q_limit use only B0 (1-term).
// mode 0: write fp32 C (+bias). mode 1: qkv epilogue — col region 0 -> g_qh
// fp16; region 1 -> g_kh/g_kl hi/lo; region 2 -> g_vh/g_vl hi/lo.
#define GSTAGE 49152
#define GEMM_SMEM (2 * GSTAGE)

__global__ void __launch_bounds__(256, 2) gemm_mma(
    const __half* __restrict__ A0,
    const __half* __restrict__ B0, const __half* __restrict__ B1,
    const float* __restrict__ bias, float* __restrict__ C,
    int M, int N, int K, int q_limit, int mode)
{
    extern __shared__ char smem[];
    const uint32_t sbase = s2u(smem);

    const int tid = threadIdx.x, wid = tid >> 5, lid = tid & 31;
    const int col0 = blockIdx.x * 128, row0 = blockIdx.y * 128;
    const int wm = wid & 3;
    const int wn = wid >> 2;
    const int npass = (col0 < q_limit) ? 1 : 2;

    const int NK = K >> 6;

    auto load_chunk = [&](int s) {
        const int kt = s << 6;
        const uint32_t sb = sbase + (uint32_t)(s & 1) * GSTAGE;
        const __half* pa0 = A0 + (size_t)row0 * K + kt;
        const __half* pb0 = B0 + (size_t)col0 * K + kt;
        const __half* pb1 = B1 + (size_t)col0 * K + kt;
        #pragma unroll
        for (int i = 0; i < 4; i++) {
            const int id = tid + i * 256;
            const int r = id >> 3, c = id & 7;
            const uint32_t sw = SWZ(r * 128 + c * 16);
            const size_t go = (size_t)r * K + c * 8;
            cp16(sb + sw,           pa0 + go);
            cp16(sb + 16384u + sw,  pb0 + go);
            if (npass == 2) cp16(sb + 32768u + sw, pb1 + go);
        }
        asm volatile("cp.async.commit_group;" ::: "memory");
    };

    float acc[16][4];
    #pragma unroll
    for (int i = 0; i < 16; i++)
        #pragma unroll
        for (int j = 0; j < 4; j++) acc[i][j] = 0.f;

    load_chunk(0);
    if (NK > 1) load_chunk(1);

    const int arow[2] = { wm * 32 + (lid & 15),
                          wm * 32 + 16 + (lid & 15) };
    const int ahalf = lid >> 4;
    const int brow_base = wn * 64 + ((lid >> 4) << 3) + (lid & 7);
    const int bhalf = (lid >> 3) & 1;

    for (int s = 0; s < NK; s++) {
        if (s + 1 < NK) asm volatile("cp.async.wait_group 1;" ::: "memory");
        else            asm volatile("cp.async.wait_group 0;" ::: "memory");
        __syncthreads();

        const uint32_t sb  = sbase + (uint32_t)(s & 1) * GSTAGE;
        const uint32_t SA0 = sb;
        const uint32_t SBT[2] = { sb + 16384u, sb + 32768u };

        #pragma unroll
        for (int ks = 0; ks < 4; ks++) {
            uint32_t ah[2][4];
            #pragma unroll
            for (int mt = 0; mt < 2; mt++) {
                const int r = arow[mt];
                const uint32_t off = (uint32_t)r * 128u
                                   + (uint32_t)(((2 * ks + ahalf) ^ (r & 7)) * 16);
                ldm4(SA0 + off, ah[mt]);
            }
            for (int pass = 0; pass < npass; pass++) {
                const uint32_t SB = SBT[pass];
                #pragma unroll
                for (int ng = 0; ng < 4; ng++) {
                    const int r = brow_base + ng * 16;
                    const uint32_t off = (uint32_t)r * 128u
                                       + (uint32_t)(((2 * ks + bhalf) ^ (r & 7)) * 16);
                    uint32_t t[4];
                    ldm4(SB + off, t);
                    #pragma unroll
                    for (int mt = 0; mt < 2; mt++) {
                        mma16816(acc[mt * 8 + 2 * ng],     ah[mt], t);
                        mma16816(acc[mt * 8 + 2 * ng + 1], ah[mt], t + 2);
                    }
                }
            }
        }
        if (s + 2 < NK) {
            __syncthreads();
            load_chunk(s + 2);
        }
    }

    if (mode == 0) {
        #pragma unroll
        for (int mt = 0; mt < 2; mt++) {
            #pragma unroll
            for (int nt = 0; nt < 8; nt++) {
                const float* c = acc[mt * 8 + nt];
                const int r0 = row0 + wm * 32 + mt * 16 + (lid >> 2);
                const int cc = col0 + wn * 64 + nt * 8 + (lid & 3) * 2;
                float b0v = 0.f, b1v = 0.f;
                if (bias) { b0v = bias[cc]; b1v = bias[cc + 1]; }
                *(float2*)&C[(size_t)r0 * N + cc] =
                    make_float2(c[0] + b0v, c[1] + b1v);
                *(float2*)&C[(size_t)(r0 + 8) * N + cc] =
                    make_float2(c[2] + b0v, c[3] + b1v);
            }
        }
    } else {
        const int region = col0 >> 10;     // 0=q, 1=k, 2=v
        __half* dh = (region == 0) ? g_qh : (region == 1) ? g_kh : g_vh;
        __half* dl = (region == 1) ? g_kl : g_vl;
        #pragma unroll
        for (int mt = 0; mt < 2; mt++) {
            #pragma unroll
            for (int nt = 0; nt < 8; nt++) {
                const float* c = acc[mt * 8 + nt];
                const int r0 = row0 + wm * 32 + mt * 16 + (lid >> 2);
                const int cl = (col0 + wn * 64 + nt * 8 + (lid & 3) * 2) & 1023;
                const size_t o0 = (size_t)r0 * DMODEL + cl;
                const size_t o1 = (size_t)(r0 + 8) * DMODEL + cl;
                if (region == 0) {
                    *(__half2*)&dh[o0] = __floats2half2_rn(c[0], c[1]);
                    *(__half2*)&dh[o1] = __floats2half2_rn(c[2], c[3]);
                } else {
                    __half2 lo0, lo1;
                    __half2 hi0 = split_hi(c[0], c[1], lo0);
                    __half2 hi1 = split_hi(c[2], c[3], lo1);
                    *(__half2*)&dh[o0] = hi0; *(__half2*)&dl[o0] = lo0;
                    *(__half2*)&dh[o1] = hi1; *(__half2*)&dl[o1] = lo1;
                }
            }
        }
    }
}

// ------------------------- fp32 -> fp16 convert ------------------------------
__global__ void __launch_bounds__(256) half_kernel(
    const float* __restrict__ in, __half* __restrict__ h, int n4)
{
    int i = blockIdx.x * blockDim.x + threadIdx.x;
    if (i >= n4) return;
    float4 v = ((const float4*)in)[i];
    *(__half2*)&h[(size_t)i * 4]     = __floats2half2_rn(v.x, v.y);
    *(__half2*)&h[(size_t)i * 4 + 2] = __floats2half2_rn(v.z, v.w);
}

// ---------------- bucket sums of x -> fp16 S (128 x 1024) --------------------
__global__ void __launch_bounds__(256) bsum_x_kernel(
    const float* __restrict__ x, __half* __restrict__ S)
{
    const int blk = blockIdx.x;            // b*64 + u
    const int b = blk >> 6, u = blk & 63;
    const float* base = x + ((size_t)(b * TLEN + u * BSZ)) * DMODEL
                          + threadIdx.x * 4;
    float4 a = make_float4(0.f, 0.f, 0.f, 0.f);
    #pragma unroll 8
    for (int i = 0; i < BSZ; i++) {
        float4 v = *(const float4*)(base + (size_t)i * DMODEL);
        a.x += v.x; a.y += v.y; a.z += v.z; a.w += v.w;
    }
    __half* d = S + (size_t)blk * DMODEL + threadIdx.x * 4;
    *(__half2*)d       = __floats2half2_rn(a.x, a.y);
    *(__half2*)(d + 2) = __floats2half2_rn(a.z, a.w);
}

// -------------------- transpose + fp16 hi/lo split: W[K,N] -> T0/T1 [N,K] ----
__global__ void __launch_bounds__(256) tsplit_kernel(
    const float* __restrict__ W, __half* __restrict__ T0,
    __half* __restrict__ T1, int K, int N)
{
    __shared__ float t[32][33];
    const int n0 = blockIdx.x * 32, k0 = blockIdx.y * 32;
    const int x = threadIdx.x & 31, y = threadIdx.x >> 5;
    #pragma unroll
    for (int j = 0; j < 32; j += 8)
        t[y + j][x] = W[(size_t)(k0 + y + j) * N + n0 + x];
    __syncthreads();
    #pragma unroll
    for (int j = 0; j < 32; j += 8) {
        float v = t[x][y + j];
        __half hi = __float2half_rn(v);
        __half lo = __float2half_rn(v - __half2float(hi));
        size_t o = (size_t)(n0 + y + j) * K + k0 + x;
        T0[o] = hi; T1[o] = lo;
    }
}

// ---------------- SortNet + Gumbel-Sinkhorn + top-1 --------------------------
// sx comes from g_sx (128 x 2048): row b*64+u; q part cols [hi*128, +128),
// k part cols [1024 + hi*128, +128).
__global__ void __launch_bounds__(256) sortnet_sinkhorn_kernel(
    const float* __restrict__ sx, const float* __restrict__ sw,
    const float* __restrict__ gum, int* __restrict__ idx_out,
    float* __restrict__ val_out)
{
    __shared__ float r[64][65];
    const int bh  = blockIdx.x;
    const int b   = bh >> 3, hi = bh & 7;
    const int tid = threadIdx.x;
    const int u   = tid >> 2;
    const int vq  = (tid & 3) * 16;

    float acc[16];
    #pragma unroll
    for (int v = 0; v < 16; v++) acc[v] = 0.f;
    const float* sq = sx + ((size_t)(b * 64 + u)) * 2048 + hi * 128;
    const float* W = sw + (size_t)hi * 256 * 64 + vq;
    for (int e = 0; e < 256; e++) {
        float s = (e < 128) ? sq[e] : sq[1024 + e - 128];
        #pragma unroll
        for (int v = 0; v < 16; v++) acc[v] += s * W[(size_t)e * 64 + v];
    }
    #pragma unroll
    for (int v = 0; v < 16; v++) {
        float R = acc[v];
        R = (R > 0.f) ? R : 0.01f * R;
        float gu = gum[((size_t)(bh * 64 + u)) * 64 + vq + v];
        float g  = -logf(-logf(gu + EPS_) + EPS_);
        r[u][vq + v] = (logf(fmaxf(R + EPS_, EPS_)) + g) / TEMP_;
    }
    __syncthreads();

    for (int it = 0; it < 5; it++) {
        if (tid < 64) {
            float m = -1e30f;
            for (int v = 0; v < 64; v++) m = fmaxf(m, r[tid][v]);
            float s = 0.f;
            for (int v = 0; v < 64; v++) s += __expf(r[tid][v] - m);
            float lse = m + logf(s);
            for (int v = 0; v < 64; v++) r[tid][v] -= lse;
        }
        __syncthreads();
        if (tid < 64) {
            float m = -1e30f;
            for (int i = 0; i < 64; i++) m = fmaxf(m, r[i][tid]);
            float s = 0.f;
            for (int i = 0; i < 64; i++) s += __expf(r[i][tid] - m);
            float lse = m + logf(s);
            for (int i = 0; i < 64; i++) r[i][tid] -= lse;
        }
        __syncthreads();
    }

    if (tid < 64) {
        int best = 0; float bm = r[tid][0];
        for (int v = 1; v < 64; v++) {
            float rv = r[tid][v];
            if (rv > bm) { bm = rv; best = v; }
        }
        idx_out[bh * 64 + tid] = best;
        val_out[bh * 64 + tid] = __expf(bm);
    }
}

// ------------------------- bucketed attention (HMMA, cp.async) ---------------
// Tiles are preformatted fp16 in gmem (q, k hi/lo, v hi/lo). pv folded in as:
// gathered-col logits *= pv pre-softmax; gathered-half p *= pv pre-PV.
#define ATT_SMEM 98304
#define OFF_Q    0u
#define OFF_KH   16384u
#define OFF_KL   49152u
#define OFF_PH   0u
#define OFF_PL   16384u
#define OFF_VH   32768u
#define OFF_VL   65536u

__global__ void __launch_bounds__(256, 2) attn_kernel(
    const int* __restrict__ idxv, const float* __restrict__ valv,
    __half* __restrict__ ao0)
{
    extern __shared__ char smem[];
    const uint32_t sbase = s2u(smem);
    __shared__ float redm[2][64], reds[2][64];

    const int blk = blockIdx.x;
    const int bh = blk >> 6, u = blk & 63;
    const int bi = bh >> 3, hi = bh & 7;
    const int tid = threadIdx.x, wid = tid >> 5, lid = tid & 31;
    const int wm = wid & 3, wn = wid >> 2;

    const int   src = idxv[blk];
    const float pv  = valv[blk];

    const size_t rowq = (size_t)(bi * TLEN + u * BSZ);
    const size_t rows = (size_t)(bi * TLEN + src * BSZ);
    const int colq = hi * DH;

    // ---- phase 1: cp.async q, k_hi, k_lo ------------------------------------
    #pragma unroll
    for (int it = 0; it < 4; it++) {       // q: 1024 x 16B
        const int id = tid + it * 256;
        const int i = id >> 4, cs = id & 15;
        const uint32_t dst = OFF_Q + (uint32_t)(cs >> 3) * 8192u
                           + SWZ((uint32_t)i * 128u + (uint32_t)(cs & 7) * 16u);
        cp16(sbase + dst, g_qh + (rowq + i) * DMODEL + colq + cs * 8);
    }
    #pragma unroll
    for (int it = 0; it < 8; it++) {       // k hi/lo: 2048 x 16B each
        const int id = tid + it * 256;
        const int j = id >> 4, cs = id & 15;
        const size_t srow = (j < 64) ? (rows + j) : (rowq + j - 64);
        const size_t go = srow * DMODEL + colq + cs * 8;
        const uint32_t off = (uint32_t)(cs >> 3) * 16384u
                           + SWZ((uint32_t)j * 128u + (uint32_t)(cs & 7) * 16u);
        cp16(sbase + OFF_KH + off, g_kh + go);
        cp16(sbase + OFF_KL + off, g_kl + go);
    }
    asm volatile("cp.async.commit_group;" ::: "memory");
    asm volatile("cp.async.wait_group 0;" ::: "memory");
    __syncthreads();

    // ---- QK -----------------------------------------------------------------
    float acc[8][4];
    #pragma unroll
    for (int a = 0; a < 8; a++)
        #pragma unroll
        for (int b = 0; b < 4; b++) acc[a][b] = 0.f;

    const int ar    = wm * 16 + (lid & 15);
    const int ahalf = lid >> 4;
    const int brow_base = wn * 64 + ((lid >> 4) << 3) + (lid & 7);
    const int bhalf = (lid >> 3) & 1;

    #pragma unroll
    for (int ks = 0; ks < 8; ks++) {
        const uint32_t sub = (uint32_t)(ks >> 2);
        const int ksl = ks & 3;
        uint32_t a4[4];
        {
            const uint32_t off = (uint32_t)ar * 128u
                               + (uint32_t)(((2 * ksl + ahalf) ^ (ar & 7)) * 16);
            ldm4(sbase + OFF_Q + sub * 8192u + off, a4);
        }
        #pragma unroll
        for (int pass = 0; pass < 2; pass++) {
            const uint32_t KB = (pass == 0 ? OFF_KH : OFF_KL) + sub * 16384u;
            #pragma unroll
            for (int ng = 0; ng < 4; ng++) {
                const int r = brow_base + ng * 16;
                const uint32_t off = (uint32_t)r * 128u
                                   + (uint32_t)(((2 * ksl + bhalf) ^ (r & 7)) * 16);
                uint32_t t[4];
                ldm4(sbase + KB + off, t);
                mma16816(acc[2 * ng],     a4, t);
                mma16816(acc[2 * ng + 1], a4, t + 2);
            }
        }
    }

    // ---- softmax over j (128); gathered cols (wn==0) get logits *= pv -------
    const int r0 = wm * 16 + (lid >> 2);
    const float lsc = SCALE_ * ((wn == 0) ? pv : 1.f);
    float m0 = -1e30f, m1 = -1e30f;
    #pragma unroll
    for (int nt = 0; nt < 8; nt++) {
        #pragma unroll
        for (int b = 0; b < 4; b++) acc[nt][b] *= lsc;
        m0 = fmaxf(m0, fmaxf(acc[nt][0], acc[nt][1]));
        m1 = fmaxf(m1, fmaxf(acc[nt][2], acc[nt][3]));
    }
    m0 = fmaxf(m0, __shfl_xor_sync(0xffffffffu, m0, 1));
    m0 = fmaxf(m0, __shfl_xor_sync(0xffffffffu, m0, 2));
    m1 = fmaxf(m1, __shfl_xor_sync(0xffffffffu, m1, 1));
    m1 = fmaxf(m1, __shfl_xor_sync(0xffffffffu, m1, 2));

    float s0 = 0.f, s1 = 0.f;
    #pragma unroll
    for (int nt = 0; nt < 8; nt++) {
        acc[nt][0] = __expf(acc[nt][0] - m0);
        acc[nt][1] = __expf(acc[nt][1] - m0);
        acc[nt][2] = __expf(acc[nt][2] - m1);
        acc[nt][3] = __expf(acc[nt][3] - m1);
        s0 += acc[nt][0] + acc[nt][1];
        s1 += acc[nt][2] + acc[nt][3];
    }
    s0 += __shfl_xor_sync(0xffffffffu, s0, 1);
    s0 += __shfl_xor_sync(0xffffffffu, s0, 2);
    s1 += __shfl_xor_sync(0xffffffffu, s1, 1);
    s1 += __shfl_xor_sync(0xffffffffu, s1, 2);

    if ((lid & 3) == 0) {
        redm[wn][r0] = m0;   reds[wn][r0] = s0;
        redm[wn][r0 + 8] = m1; reds[wn][r0 + 8] = s1;
    }
    __syncthreads();     // all warps past QK smem reads

    {
        const float mo0 = redm[wn ^ 1][r0],     so0 = reds[wn ^ 1][r0];
        const float mo1 = redm[wn ^ 1][r0 + 8], so1 = reds[wn ^ 1][r0 + 8];
        const float M0 = fmaxf(m0, mo0), M1 = fmaxf(m1, mo1);
        const float S0 = s0 * __expf(m0 - M0) + so0 * __expf(mo0 - M0);
        const float S1 = s1 * __expf(m1 - M1) + so1 * __expf(mo1 - M1);
        // gathered half (wn==0): p *= pv for the PV product
        const float pf = (wn == 0) ? pv : 1.f;
        const float f0 = pf * __expf(m0 - M0) / S0;
        const float f1 = pf * __expf(m1 - M1) / S1;

        #pragma unroll
        for (int nt = 0; nt < 8; nt++) {
            const float p0 = acc[nt][0] * f0, p1 = acc[nt][1] * f0;
            const float p2 = acc[nt][2] * f1, p3 = acc[nt][3] * f1;
            const int j6 = nt * 8 + (lid & 3) * 2;
            const uint32_t sw0 = SWZ((uint32_t)r0 * 128u + (uint32_t)j6 * 2u);
            const uint32_t sw1 = SWZ((uint32_t)(r0 + 8) * 128u + (uint32_t)j6 * 2u);
            const uint32_t psub = (uint32_t)wn * 8192u;
            __half2 lo0, lo1;
            __half2 hi0 = split_hi(p0, p1, lo0);
            __half2 hi1 = split_hi(p2, p3, lo1);
            *(__half2*)(smem + OFF_PH + psub + sw0) = hi0;
            *(__half2*)(smem + OFF_PH + psub + sw1) = hi1;
            *(__half2*)(smem + OFF_PL + psub + sw0) = lo0;
            *(__half2*)(smem + OFF_PL + psub + sw1) = lo1;
        }
    }

    // ---- phase 2: cp.async v_hi, v_lo (over k region) -----------------------
    #pragma unroll
    for (int it = 0; it < 8; it++) {
        const int id = tid + it * 256;
        const int j = id >> 4, cs = id & 15;
        const size_t srow = (j < 64) ? (rows + j) : (rowq + j - 64);
        const size_t go = srow * DMODEL + colq + cs * 8;
        const uint32_t off = (uint32_t)(cs >> 3) * 16384u
                           + SWZ((uint32_t)j * 128u + (uint32_t)(cs & 7) * 16u);
        cp16(sbase + OFF_VH + off, g_vh + go);
        cp16(sbase + OFF_VL + off, g_vl + go);
    }
    asm volatile("cp.async.commit_group;" ::: "memory");
    asm volatile("cp.async.wait_group 0;" ::: "memory");
    __syncthreads();

    // ---- PV -----------------------------------------------------------------
    #pragma unroll
    for (int a = 0; a < 8; a++)
        #pragma unroll
        for (int b = 0; b < 4; b++) acc[a][b] = 0.f;

    const int vj_off = (lid & 7) + (((lid >> 3) & 1) << 3);
    const int veseg  = (lid >> 4) << 3;

    #pragma unroll
    for (int ks = 0; ks < 8; ks++) {
        const uint32_t psub = (uint32_t)(ks >> 2) * 8192u;
        const int ksl = ks & 3;
        uint32_t aph[4], apl[4];
        {
            const uint32_t off = (uint32_t)ar * 128u
                               + (uint32_t)(((2 * ksl + ahalf) ^ (ar & 7)) * 16);
            ldm4(sbase + OFF_PH + psub + off, aph);
            ldm4(sbase + OFF_PL + psub + off, apl);
        }
        const int vj = ks * 16 + vj_off;
        #pragma unroll
        for (int ng = 0; ng < 4; ng++) {
            const int e6 = ng * 16 + veseg;
            const uint32_t off = (uint32_t)vj * 128u
                               + (uint32_t)((((e6 >> 3) & 7) ^ (vj & 7)) * 16);
            const uint32_t vsub = (uint32_t)wn * 16384u;
            uint32_t th[4], tl[4];
            ldm4t(sbase + OFF_VH + vsub + off, th);
            ldm4t(sbase + OFF_VL + vsub + off, tl);
            mma16816(acc[2 * ng],     aph, th);
            mma16816(acc[2 * ng + 1], aph, th + 2);
            mma16816(acc[2 * ng],     aph, tl);
            mma16816(acc[2 * ng + 1], aph, tl + 2);
            mma16816(acc[2 * ng],     apl, th);
            mma16816(acc[2 * ng + 1], apl, th + 2);
        }
    }

    #pragma unroll
    for (int nt = 0; nt < 8; nt++) {
        const int e = wn * 64 + nt * 8 + (lid & 3) * 2;
        const size_t o0 = (rowq + r0) * DMODEL + colq + e;
        const size_t o1 = (rowq + r0 + 8) * DMODEL + colq + e;
        *(__half2*)&ao0[o0] = __floats2half2_rn(acc[nt][0], acc[nt][1]);
        *(__half2*)&ao0[o1] = __floats2half2_rn(acc[nt][2], acc[nt][3]);
    }
}

// ------------------------- launcher ------------------------------------------
extern "C" void kernel_launch(void* const* d_in, const int* in_sizes, int n_in,
                              void* d_out, int out_size)
{
    const float* x      = (const float*)d_in[0];
    const float* gumbel = (const float*)d_in[1];
    const float* w_qkv  = (const float*)d_in[2];
    const float* sort_w = (const float*)d_in[3];
    const float* w_out  = (const float*)d_in[4];
    const float* b_out  = (const float*)d_in[5];
    float* out = (float*)d_out;

    float *sx, *val; int* idx;
    __half *x0, *S, *wq0, *wq1, *wo0, *wo1, *ao0;
    cudaGetSymbolAddress((void**)&sx,  g_sx);
    cudaGetSymbolAddress((void**)&idx, g_idx);
    cudaGetSymbolAddress((void**)&val, g_val);
    cudaGetSymbolAddress((void**)&x0,  g_x0);
    cudaGetSymbolAddress((void**)&S,   g_S);
    cudaGetSymbolAddress((void**)&wq0, g_wq0);
    cudaGetSymbolAddress((void**)&wq1, g_wq1);
    cudaGetSymbolAddress((void**)&wo0, g_wo0);
    cudaGetSymbolAddress((void**)&wo1, g_wo1);
    cudaGetSymbolAddress((void**)&ao0, g_ao0);

    cudaFuncSetAttribute(gemm_mma,
                         cudaFuncAttributeMaxDynamicSharedMemorySize, GEMM_SMEM);
    cudaFuncSetAttribute(attn_kernel,
                         cudaFuncAttributeMaxDynamicSharedMemorySize, ATT_SMEM);

    // 0) prep: x->fp16, bucket sums of x, weight transposes+splits
    {
        int n4 = NROWS * DMODEL / 4;
        half_kernel<<<(n4 + 255) / 256, 256>>>(x, x0, n4);
    }
    bsum_x_kernel<<<128, 256>>>(x, S);
    tsplit_kernel<<<dim3(QKVC / 32, DMODEL / 32), 256>>>(w_qkv, wq0, wq1, DMODEL, QKVC);
    tsplit_kernel<<<dim3(DMODEL / 32, DMODEL / 32), 256>>>(w_out, wo0, wo1, DMODEL, DMODEL);

    // 1) qkv GEMM, fused epilogue -> q fp16 / k,v hi+lo (q cols 1-term)
    gemm_mma<<<dim3(QKVC / 128, NROWS / 128), 256, GEMM_SMEM>>>(
        x0, wq0, wq1, nullptr, nullptr, NROWS, QKVC, DMODEL, 1024, 1);

    // 2) sx = bucket_sum(x) @ w_qkv[:, :2048]  (2-term)
    gemm_mma<<<dim3(2048 / 128, 1), 256, GEMM_SMEM>>>(
        S, wq0, wq1, nullptr, sx, 128, 2048, DMODEL, 0, 0);

    // 3) SortNet + gumbel-sinkhorn + top-1
    sortnet_sinkhorn_kernel<<<BH, 256>>>(sx, sort_w, gumbel, idx, val);

    // 4) bucketed attention (all fp16, cp.async tiles, pv folded)
    attn_kernel<<<BH * NBUCK, 256, ATT_SMEM>>>(idx, val, ao0);

    // 5) out = ao @ w_out + b_out  (2-term)
    gemm_mma<<<dim3(DMODEL / 128, NROWS / 128), 256, GEMM_SMEM>>>(
        ao0, wo0, wo1, b_out, out, NROWS, DMODEL, DMODEL, 0, 0);
}